// round 15
// baseline (speedup 1.0000x reference)
#include <cuda_runtime.h>
#include <cuda_fp16.h>

// Problem constants
#define BATCH 4
#define CH    256
#define G     8
#define HD    32
#define L     3136      // 56*56
#define BG    32        // BATCH*G
#define NT    49        // 64-wide j tiles
#define NKT   25        // 128-wide k tiles (last covers only 64 cols)
#define LOG2E 1.4426950408889634f

// Scratch (static device arrays). fp16 operands, fp32 stats.
__device__ __align__(256) __half g_qh[(size_t)BG * L * HD];  // (bg, l, d) q*log2e
__device__ __align__(256) __half g_kh[(size_t)BG * L * HD];  // (bg, k, d) transposed
__device__ __align__(256) __half g_vh[(size_t)BG * HD * L];  // (bg, d, l)
__device__ __align__(256) float  g_lz[BG * L];               // -log2(row sum)

struct alignas(16) H8 { __half2 h[4]; };

// ---------------------------------------------------------------------------
// helpers
// ---------------------------------------------------------------------------
__device__ __forceinline__ float ex2(float x) {
    float r;
    asm("ex2.approx.ftz.f32 %0, %1;" : "=f"(r) : "f"(x));
    return r;
}

__device__ __forceinline__ void cp16(void* smem_dst, const void* gsrc) {
    unsigned s = (unsigned)__cvta_generic_to_shared(smem_dst);
    asm volatile("cp.async.cg.shared.global [%0], [%1], 16;" :: "r"(s), "l"(gsrc));
}
#define CP_COMMIT() asm volatile("cp.async.commit_group;")
#define CP_WAIT0()  asm volatile("cp.async.wait_group 0;")

// fp16 mma m16n8k16, fp32 accum.
// A row-major frag: a0={A[g][2t],A[g][2t+1]} a1={A[g+8][..]} a2={A[g][2t+8..]} a3={A[g+8][2t+8..]}
// B frag: b0={B[2t][g],B[2t+1][g]} b1={B[2t+8][g],B[2t+9][g]}
// C: c0=(g,2t) c1=(g,2t+1) c2=(g+8,2t) c3=(g+8,2t+1)
__device__ __forceinline__ void mma_f16(float c[4],
                                        unsigned a0, unsigned a1, unsigned a2, unsigned a3,
                                        unsigned b0, unsigned b1)
{
    asm volatile(
        "mma.sync.aligned.m16n8k16.row.col.f32.f16.f16.f32 "
        "{%0,%1,%2,%3}, {%4,%5,%6,%7}, {%8,%9}, {%0,%1,%2,%3};"
        : "+f"(c[0]), "+f"(c[1]), "+f"(c[2]), "+f"(c[3])
        : "r"(a0), "r"(a1), "r"(a2), "r"(a3), "r"(b0), "r"(b1));
}

__device__ __forceinline__ unsigned ldh2(const __half* p) {
    return *(const unsigned*)p;   // 4B-aligned half2 load
}

// ---------------------------------------------------------------------------
// Kernel 1: grouped 1x1 conv -> q (scaled, fp16, [l][d]), k (fp16, [k][d]), v ([d][l]).
// grid (49, 32), block 256. x staged transposed [l][d]; float4 smem reads.
// ---------------------------------------------------------------------------
__global__ void __launch_bounds__(256, 3)
qkv_kernel(const float* __restrict__ x,
           const float* __restrict__ Wq, const float* __restrict__ bq,
           const float* __restrict__ Wk, const float* __restrict__ bk,
           const float* __restrict__ Wv, const float* __restrict__ bv)
{
    int bg = blockIdx.y;
    int l0 = blockIdx.x * 64;
    int b = bg >> 3, g = bg & 7;

    __shared__ float wqs[HD * HD], wks[HD * HD], wvs[HD * HD];
    __shared__ float bqs[HD], bks[HD], bvs[HD];
    __shared__ float xst[64][36];   // [l][d], pad 36

    int tid = threadIdx.x;
    for (int i = tid; i < HD * HD; i += 256) {
        wqs[i] = Wq[g * HD * HD + i] * LOG2E;
        wks[i] = Wk[g * HD * HD + i];
        wvs[i] = Wv[g * HD * HD + i];
    }
    if (tid < HD) {
        bqs[tid] = bq[g * HD + tid] * LOG2E;
        bks[tid] = bk[g * HD + tid];
        bvs[tid] = bv[g * HD + tid];
    }
    const float* xp = x + ((size_t)b * CH + g * HD) * L + l0;
    for (int i = tid; i < HD * 64; i += 256) {
        int d = i >> 6, l = i & 63;
        xst[l][d] = xp[(size_t)d * L + l];   // coalesced gmem read over l
    }
    __syncthreads();

    int l  = tid & 63;
    int o0 = (tid >> 6) * 8;
    float qa[8], ka[8], va[8];
#pragma unroll
    for (int r = 0; r < 8; r++) { qa[r] = bqs[o0 + r]; ka[r] = bks[o0 + r]; va[r] = bvs[o0 + r]; }

#pragma unroll
    for (int i4 = 0; i4 < 8; i4++) {
        float4 xv = *(const float4*)&xst[l][i4 * 4];
#pragma unroll
        for (int r = 0; r < 8; r++) {
            int wo = (o0 + r) * HD + i4 * 4;
            float4 wq = *(const float4*)&wqs[wo];
            float4 wk = *(const float4*)&wks[wo];
            float4 wv = *(const float4*)&wvs[wo];
            qa[r] += wq.x * xv.x + wq.y * xv.y + wq.z * xv.z + wq.w * xv.w;
            ka[r] += wk.x * xv.x + wk.y * xv.y + wk.z * xv.z + wk.w * xv.w;
            va[r] += wv.x * xv.x + wv.y * xv.y + wv.z * xv.z + wv.w * xv.w;
        }
    }

    size_t base = ((size_t)bg * L + l0 + l) * HD + o0;
    H8 qp8, kp8;
#pragma unroll
    for (int r = 0; r < 8; r += 2) {
        qp8.h[r >> 1] = __floats2half2_rn(qa[r], qa[r + 1]);
        kp8.h[r >> 1] = __floats2half2_rn(ka[r], ka[r + 1]);
    }
    *(H8*)&g_qh[base] = qp8;
    *(H8*)&g_kh[base] = kp8;
    size_t vbase = ((size_t)bg * HD + o0) * L + l0 + l;
#pragma unroll
    for (int r = 0; r < 8; r++)
        g_vh[vbase + (size_t)r * L] = __float2half_rn(va[r]);
}

// ---------------------------------------------------------------------------
// Kernel 2: Z_j = sum_k exp2(e[j,k]); stores -log2(Z).
// grid (49 j-tiles, 32 bg), block 256. Block tile 64j x 128k. fp32 MUFU.
// ---------------------------------------------------------------------------
__global__ void __launch_bounds__(256) pass1_kernel()
{
    int bg = blockIdx.y;
    int j0 = blockIdx.x * 64;

    __shared__ __half qs[64][40];        // [j][d]
    __shared__ __half ks[2][128][40];    // [buf][kcol][d]
    __shared__ float zsh[64];

    int tid = threadIdx.x;
    int w = tid >> 5, lane = tid & 31;
    int g = lane >> 2, t = lane & 3;
    int wj = w >> 2, wk = w & 3;
    int m0 = wj * 32, nb = wk * 32;

    const __half* qp = g_qh + (size_t)bg * L * HD;
    const __half* kp = g_kh + (size_t)bg * L * HD;

#pragma unroll
    for (int r = 0; r < 2; r++) {
        int task = tid + 256 * r;
        int row = task >> 2, ch = task & 3;
        cp16(&ks[0][row][ch * 8], kp + (size_t)row * HD + ch * 8);
    }
    CP_COMMIT();

    {
        int row = tid >> 2, ch = tid & 3;
        *(uint4*)&qs[row][ch * 8] = *(const uint4*)(qp + (size_t)(j0 + row) * HD + ch * 8);
    }
    if (tid < 64) zsh[tid] = 0.f;

    float s[2][2] = {{0.f, 0.f}, {0.f, 0.f}};
    int buf = 0;

    for (int kt = 0; kt < NKT; kt++) {
        CP_WAIT0();
        __syncthreads();

        if (kt + 1 < NKT) {
            int kbase = (kt + 1) * 128;
#pragma unroll
            for (int r = 0; r < 2; r++) {
                int task = tid + 256 * r;
                int row = task >> 2, ch = task & 3;
                int col = kbase + row;
                if (col < L)
                    cp16(&ks[buf ^ 1][row][ch * 8], kp + (size_t)col * HD + ch * 8);
            }
            CP_COMMIT();
        }

        float e[2][4][4];
#pragma unroll
        for (int mt = 0; mt < 2; mt++)
#pragma unroll
            for (int nt = 0; nt < 4; nt++)
#pragma unroll
                for (int c = 0; c < 4; c++) e[mt][nt][c] = 0.f;

#pragma unroll
        for (int s16 = 0; s16 < 2; s16++) {
            int kd = s16 * 16;
            unsigned a[2][4];
#pragma unroll
            for (int mt = 0; mt < 2; mt++) {
                int r = m0 + mt * 16 + g;
                a[mt][0] = ldh2(&qs[r    ][kd + 2 * t    ]);
                a[mt][1] = ldh2(&qs[r + 8][kd + 2 * t    ]);
                a[mt][2] = ldh2(&qs[r    ][kd + 2 * t + 8]);
                a[mt][3] = ldh2(&qs[r + 8][kd + 2 * t + 8]);
            }
#pragma unroll
            for (int nt = 0; nt < 4; nt++) {
                int n = nb + nt * 8 + g;
                unsigned b0 = ldh2(&ks[buf][n][kd + 2 * t    ]);
                unsigned b1 = ldh2(&ks[buf][n][kd + 2 * t + 8]);
                mma_f16(e[0][nt], a[0][0], a[0][1], a[0][2], a[0][3], b0, b1);
                mma_f16(e[1][nt], a[1][0], a[1][1], a[1][2], a[1][3], b0, b1);
            }
        }

        if (kt < NKT - 1 || wk < 2) {
#pragma unroll
            for (int mt = 0; mt < 2; mt++)
#pragma unroll
                for (int nt = 0; nt < 4; nt++) {
                    s[mt][0] += ex2(e[mt][nt][0]) + ex2(e[mt][nt][1]);
                    s[mt][1] += ex2(e[mt][nt][2]) + ex2(e[mt][nt][3]);
                }
        }
        buf ^= 1;
    }

#pragma unroll
    for (int mask = 1; mask <= 2; mask <<= 1)
#pragma unroll
        for (int mt = 0; mt < 2; mt++)
#pragma unroll
            for (int r = 0; r < 2; r++)
                s[mt][r] += __shfl_xor_sync(0xffffffffu, s[mt][r], mask);
    if (t == 0) {
        atomicAdd(&zsh[m0 + g     ], s[0][0]);
        atomicAdd(&zsh[m0 + g + 8 ], s[0][1]);
        atomicAdd(&zsh[m0 + g + 16], s[1][0]);
        atomicAdd(&zsh[m0 + g + 24], s[1][1]);
    }
    __syncthreads();
    if (tid < 64) g_lz[bg * L + j0 + tid] = -log2f(zsh[tid]);
}

// ---------------------------------------------------------------------------
// Kernel 3: out[d,k] = sum_j exp2(e[j,k] + lz_j) * v[d,j]  (+ x residual)
// grid (25 k-tiles, 32 bg), block 256, dynamic smem (~48.9 KB).
// QK computes E^T (A=K m=k-dim, B=Q n=j-dim) -> C pairs adjacent in j ->
// packed half2 exp stores into psT[k][j]. Warp (w>>1: 32k, w&1: 32j).
// PV: kh=w>>2 (j-half), wm=(w>>1)&1 (16 d rows), wn=w&1 (64 k cols).
// ---------------------------------------------------------------------------
__global__ void __launch_bounds__(256) pass2_kernel(const float* __restrict__ x,
                                                    float* __restrict__ out)
{
    extern __shared__ __half smh[];
    __half (*ks2)[40] = (__half(*)[40])smh;                  // 128k x 40  (5120)
    __half (*qs)[40]  = (__half(*)[40])(smh + 5120);         // 2 x 64j x 40 (5120)
    __half (*ws)[72]  = (__half(*)[72])(smh + 10240);        // 2 x 32d x 72 (4608)
    __half (*psT)[72] = (__half(*)[72])(smh + 14848);        // 128k x 72j (9216)
    float* lzsh       = (float*)(smh + 24064);               // 2 x 64 floats
    float* red        = (float*)psT;                          // epilogue scratch [32][130]

    int bg = blockIdx.y;
    int k0 = blockIdx.x * 128;
    int tid = threadIdx.x;
    int w = tid >> 5, lane = tid & 31;
    int g = lane >> 2, t = lane & 3;
    int mE = (w >> 1) * 32;            // E^T k-base for this warp
    int nE = (w & 1) * 32;             // E^T j-base
    int kh = w >> 2, wm = (w >> 1) & 1, wn = w & 1;
    int m0p = wm * 16, nbp = wn * 64;

    const __half* qp  = g_qh + (size_t)bg * L * HD;
    const __half* kp  = g_kh + (size_t)bg * L * HD;
    const __half* vp  = g_vh + (size_t)bg * HD * L;
    const float*  lzp = g_lz + bg * L;

    {
        int row = tid >> 2, ch = tid & 3;
        cp16(&qs[row][ch * 8], qp + (size_t)row * HD + ch * 8);
        int vrow = tid >> 3, vch = tid & 7;
        cp16(&ws[vrow][vch * 8], vp + (size_t)vrow * L + vch * 8);
        if (tid < 16) cp16(&lzsh[tid * 4], lzp + tid * 4);
        CP_COMMIT();
    }

#pragma unroll
    for (int r = 0; r < 2; r++) {
        int task = tid + 256 * r;
        int row = task >> 2, ch = task & 3;
        int col = k0 + row;
        if (col < L)
            *(uint4*)&ks2[row][ch * 8] = *(const uint4*)(kp + (size_t)col * HD + ch * 8);
        else
            *(uint4*)&ks2[row][ch * 8] = make_uint4(0, 0, 0, 0);
    }

    float acc[8][4];
#pragma unroll
    for (int nt = 0; nt < 8; nt++)
#pragma unroll
        for (int c = 0; c < 4; c++) acc[nt][c] = 0.f;

    int buf = 0;
    for (int jt = 0; jt < NT; jt++) {
        CP_WAIT0();
        __syncthreads();

        if (jt + 1 < NT) {
            int jn = (jt + 1) * 64;
            int ob = buf ^ 1;
            int row = tid >> 2, ch = tid & 3;
            cp16(&qs[ob * 64 + row][ch * 8], qp + (size_t)(jn + row) * HD + ch * 8);
            int vrow = tid >> 3, vch = tid & 7;
            cp16(&ws[ob * 32 + vrow][vch * 8], vp + (size_t)vrow * L + jn + vch * 8);
            if (tid < 16) cp16(&lzsh[ob * 64 + tid * 4], lzp + jn + tid * 4);
            CP_COMMIT();
        }

        // ---- E^T = K Q^T tile (128k x 64j): A = K (m=k), B = Q (n=j) ----
        float e[2][4][4];
#pragma unroll
        for (int mt = 0; mt < 2; mt++)
#pragma unroll
            for (int nt = 0; nt < 4; nt++)
#pragma unroll
                for (int c = 0; c < 4; c++) e[mt][nt][c] = 0.f;

#pragma unroll
        for (int s16 = 0; s16 < 2; s16++) {
            int kd = s16 * 16;
            unsigned a[2][4];
#pragma unroll
            for (int mt = 0; mt < 2; mt++) {
                int r = mE + mt * 16 + g;
                a[mt][0] = ldh2(&ks2[r    ][kd + 2 * t    ]);
                a[mt][1] = ldh2(&ks2[r + 8][kd + 2 * t    ]);
                a[mt][2] = ldh2(&ks2[r    ][kd + 2 * t + 8]);
                a[mt][3] = ldh2(&ks2[r + 8][kd + 2 * t + 8]);
            }
#pragma unroll
            for (int nt = 0; nt < 4; nt++) {
                int n = buf * 64 + nE + nt * 8 + g;
                unsigned b0 = ldh2(&qs[n][kd + 2 * t    ]);
                unsigned b1 = ldh2(&qs[n][kd + 2 * t + 8]);
                mma_f16(e[0][nt], a[0][0], a[0][1], a[0][2], a[0][3], b0, b1);
                mma_f16(e[1][nt], a[1][0], a[1][1], a[1][2], a[1][3], b0, b1);
            }
        }

        // ---- P = exp2(E + lz_j) <= 1: C pairs adjacent in j -> packed STS.32 ----
#pragma unroll
        for (int nt = 0; nt < 4; nt++) {
            int jc = nE + nt * 8 + 2 * t;
            float lz0 = lzsh[buf * 64 + jc];
            float lz1 = lzsh[buf * 64 + jc + 1];
#pragma unroll
            for (int mt = 0; mt < 2; mt++) {
                int kr = mE + mt * 16 + g;
                __half2 p0 = __floats2half2_rn(ex2(e[mt][nt][0] + lz0),
                                               ex2(e[mt][nt][1] + lz1));
                __half2 p1 = __floats2half2_rn(ex2(e[mt][nt][2] + lz0),
                                               ex2(e[mt][nt][3] + lz1));
                *(__half2*)&psT[kr    ][jc] = p0;
                *(__half2*)&psT[kr + 8][jc] = p1;
            }
        }
        __syncthreads();

        // ---- acc += V * P  (M=32 d, N=128 k, K=64 j; j split across kh) ----
#pragma unroll
        for (int s16 = 0; s16 < 2; s16++) {
            int kd = kh * 32 + s16 * 16;
            unsigned a0 = ldh2(&ws[buf * 32 + m0p + g    ][kd + 2 * t    ]);
            unsigned a1 = ldh2(&ws[buf * 32 + m0p + g + 8][kd + 2 * t    ]);
            unsigned a2 = ldh2(&ws[buf * 32 + m0p + g    ][kd + 2 * t + 8]);
            unsigned a3 = ldh2(&ws[buf * 32 + m0p + g + 8][kd + 2 * t + 8]);
#pragma unroll
            for (int nt = 0; nt < 8; nt++) {
                int n = nbp + nt * 8 + g;
                unsigned b0 = ldh2(&psT[n][kd + 2 * t    ]);
                unsigned b1 = ldh2(&psT[n][kd + 2 * t + 8]);
                mma_f16(acc[nt], a0, a1, a2, a3, b0, b1);
            }
        }
        buf ^= 1;
    }

    // ---- split-K reduction across kh pairs (reuse psT as fp32 scratch) ----
    __syncthreads();
    if (kh == 1) {
#pragma unroll
        for (int nt = 0; nt < 8; nt++) {
            int col = nbp + nt * 8 + 2 * t;
            *(float2*)&red[(m0p + g    ) * 130 + col] = make_float2(acc[nt][0], acc[nt][1]);
            *(float2*)&red[(m0p + g + 8) * 130 + col] = make_float2(acc[nt][2], acc[nt][3]);
        }
    }
    __syncthreads();
    if (kh == 0) {
        int b = bg >> 3, gh = bg & 7;
#pragma unroll
        for (int nt = 0; nt < 8; nt++) {
            int col = nbp + nt * 8 + 2 * t;
            float2 r0 = *(float2*)&red[(m0p + g    ) * 130 + col];
            float2 r1 = *(float2*)&red[(m0p + g + 8) * 130 + col];
            int gcol = k0 + col;
            if (gcol < L) {
                size_t b0 = ((size_t)b * CH + gh * HD + m0p + g) * L + gcol;
                size_t b1 = b0 + (size_t)8 * L;
                out[b0    ] = acc[nt][0] + r0.x + x[b0    ];
                out[b0 + 1] = acc[nt][1] + r0.y + x[b0 + 1];
                out[b1    ] = acc[nt][2] + r1.x + x[b1    ];
                out[b1 + 1] = acc[nt][3] + r1.y + x[b1 + 1];
            }
        }
    }
}

// ---------------------------------------------------------------------------
extern "C" void kernel_launch(void* const* d_in, const int* in_sizes, int n_in,
                              void* d_out, int out_size)
{
    (void)in_sizes; (void)n_in; (void)out_size;
    const float* x  = (const float*)d_in[0];
    const float* Wq = (const float*)d_in[1];
    const float* bq = (const float*)d_in[2];
    const float* Wk = (const float*)d_in[3];
    const float* bk = (const float*)d_in[4];
    const float* Wv = (const float*)d_in[5];
    const float* bv = (const float*)d_in[6];
    float* out = (float*)d_out;

    const int SMEM2 = 24320 * 2 + 256;
    cudaFuncSetAttribute(pass2_kernel, cudaFuncAttributeMaxDynamicSharedMemorySize, SMEM2);

    qkv_kernel<<<dim3(NT, BG), 256>>>(x, Wq, bq, Wk, bk, Wv, bv);
    pass1_kernel<<<dim3(NT, BG), 256>>>();
    pass2_kernel<<<dim3(NKT, BG), 256, SMEM2>>>(x, out);
}

// round 16
// speedup vs baseline: 1.0301x; 1.0301x over previous
#include <cuda_runtime.h>
#include <cuda_fp16.h>

// Problem constants
#define BATCH 4
#define CH    256
#define G     8
#define HD    32
#define L     3136      // 56*56
#define BG    32        // BATCH*G
#define NT    49        // 64-wide j tiles
#define NKT   25        // 128-wide k tiles (last covers only 64 cols)
#define LOG2E 1.4426950408889634f

// Scratch (static device arrays). fp16 operands, fp32 stats.
__device__ __align__(256) __half g_qh[(size_t)BG * L * HD];  // (bg, l, d) q*log2e
__device__ __align__(256) __half g_kh[(size_t)BG * L * HD];  // (bg, k, d) transposed
__device__ __align__(256) __half g_vh[(size_t)BG * HD * L];  // (bg, d, l)
__device__ __align__(256) float  g_lz[BG * L];               // -log2(row sum)

struct alignas(16) H8 { __half2 h[4]; };

// ---------------------------------------------------------------------------
// helpers
// ---------------------------------------------------------------------------
__device__ __forceinline__ float ex2(float x) {
    float r;
    asm("ex2.approx.ftz.f32 %0, %1;" : "=f"(r) : "f"(x));
    return r;
}

__device__ __forceinline__ void cp16(void* smem_dst, const void* gsrc) {
    unsigned s = (unsigned)__cvta_generic_to_shared(smem_dst);
    asm volatile("cp.async.cg.shared.global [%0], [%1], 16;" :: "r"(s), "l"(gsrc));
}
#define CP_COMMIT() asm volatile("cp.async.commit_group;")
#define CP_WAIT0()  asm volatile("cp.async.wait_group 0;")

// fp16 mma m16n8k16, fp32 accum.
// A row-major frag: a0={A[g][2t],A[g][2t+1]} a1={A[g+8][..]} a2={A[g][2t+8..]} a3={A[g+8][2t+8..]}
// B frag: b0={B[2t][g],B[2t+1][g]} b1={B[2t+8][g],B[2t+9][g]}
// C: c0=(g,2t) c1=(g,2t+1) c2=(g+8,2t) c3=(g+8,2t+1)
__device__ __forceinline__ void mma_f16(float c[4],
                                        unsigned a0, unsigned a1, unsigned a2, unsigned a3,
                                        unsigned b0, unsigned b1)
{
    asm volatile(
        "mma.sync.aligned.m16n8k16.row.col.f32.f16.f16.f32 "
        "{%0,%1,%2,%3}, {%4,%5,%6,%7}, {%8,%9}, {%0,%1,%2,%3};"
        : "+f"(c[0]), "+f"(c[1]), "+f"(c[2]), "+f"(c[3])
        : "r"(a0), "r"(a1), "r"(a2), "r"(a3), "r"(b0), "r"(b1));
}

__device__ __forceinline__ unsigned ldh2(const __half* p) {
    return *(const unsigned*)p;   // 4B-aligned half2 load
}

// ---------------------------------------------------------------------------
// Kernel 1: grouped 1x1 conv -> q (scaled, fp16, [l][d]), k (fp16, [k][d]), v ([d][l]).
// grid (49, 32), block 256. x staged transposed [l][d]; float4 smem reads.
// ---------------------------------------------------------------------------
__global__ void __launch_bounds__(256, 3)
qkv_kernel(const float* __restrict__ x,
           const float* __restrict__ Wq, const float* __restrict__ bq,
           const float* __restrict__ Wk, const float* __restrict__ bk,
           const float* __restrict__ Wv, const float* __restrict__ bv)
{
    int bg = blockIdx.y;
    int l0 = blockIdx.x * 64;
    int b = bg >> 3, g = bg & 7;

    __shared__ float wqs[HD * HD], wks[HD * HD], wvs[HD * HD];
    __shared__ float bqs[HD], bks[HD], bvs[HD];
    __shared__ float xst[64][36];   // [l][d], pad 36

    int tid = threadIdx.x;
    for (int i = tid; i < HD * HD; i += 256) {
        wqs[i] = Wq[g * HD * HD + i] * LOG2E;
        wks[i] = Wk[g * HD * HD + i];
        wvs[i] = Wv[g * HD * HD + i];
    }
    if (tid < HD) {
        bqs[tid] = bq[g * HD + tid] * LOG2E;
        bks[tid] = bk[g * HD + tid];
        bvs[tid] = bv[g * HD + tid];
    }
    const float* xp = x + ((size_t)b * CH + g * HD) * L + l0;
    for (int i = tid; i < HD * 64; i += 256) {
        int d = i >> 6, l = i & 63;
        xst[l][d] = xp[(size_t)d * L + l];   // coalesced gmem read over l
    }
    __syncthreads();

    int l  = tid & 63;
    int o0 = (tid >> 6) * 8;
    float qa[8], ka[8], va[8];
#pragma unroll
    for (int r = 0; r < 8; r++) { qa[r] = bqs[o0 + r]; ka[r] = bks[o0 + r]; va[r] = bvs[o0 + r]; }

#pragma unroll
    for (int i4 = 0; i4 < 8; i4++) {
        float4 xv = *(const float4*)&xst[l][i4 * 4];
#pragma unroll
        for (int r = 0; r < 8; r++) {
            int wo = (o0 + r) * HD + i4 * 4;
            float4 wq = *(const float4*)&wqs[wo];
            float4 wk = *(const float4*)&wks[wo];
            float4 wv = *(const float4*)&wvs[wo];
            qa[r] += wq.x * xv.x + wq.y * xv.y + wq.z * xv.z + wq.w * xv.w;
            ka[r] += wk.x * xv.x + wk.y * xv.y + wk.z * xv.z + wk.w * xv.w;
            va[r] += wv.x * xv.x + wv.y * xv.y + wv.z * xv.z + wv.w * xv.w;
        }
    }

    size_t base = ((size_t)bg * L + l0 + l) * HD + o0;
    H8 qp8, kp8;
#pragma unroll
    for (int r = 0; r < 8; r += 2) {
        qp8.h[r >> 1] = __floats2half2_rn(qa[r], qa[r + 1]);
        kp8.h[r >> 1] = __floats2half2_rn(ka[r], ka[r + 1]);
    }
    *(H8*)&g_qh[base] = qp8;
    *(H8*)&g_kh[base] = kp8;
    size_t vbase = ((size_t)bg * HD + o0) * L + l0 + l;
#pragma unroll
    for (int r = 0; r < 8; r++)
        g_vh[vbase + (size_t)r * L] = __float2half_rn(va[r]);
}

// ---------------------------------------------------------------------------
// Kernel 2: Z_j = sum_k exp2(e[j,k]); stores -log2(Z).
// grid (49 j-tiles, 32 bg), block 256. Block tile 64j x 128k. fp32 MUFU.
// ---------------------------------------------------------------------------
__global__ void __launch_bounds__(256) pass1_kernel()
{
    int bg = blockIdx.y;
    int j0 = blockIdx.x * 64;

    __shared__ __half qs[64][40];        // [j][d]
    __shared__ __half ks[2][128][40];    // [buf][kcol][d]
    __shared__ float zsh[64];

    int tid = threadIdx.x;
    int w = tid >> 5, lane = tid & 31;
    int g = lane >> 2, t = lane & 3;
    int wj = w >> 2, wk = w & 3;
    int m0 = wj * 32, nb = wk * 32;

    const __half* qp = g_qh + (size_t)bg * L * HD;
    const __half* kp = g_kh + (size_t)bg * L * HD;

#pragma unroll
    for (int r = 0; r < 2; r++) {
        int task = tid + 256 * r;
        int row = task >> 2, ch = task & 3;
        cp16(&ks[0][row][ch * 8], kp + (size_t)row * HD + ch * 8);
    }
    CP_COMMIT();

    {
        int row = tid >> 2, ch = tid & 3;
        *(uint4*)&qs[row][ch * 8] = *(const uint4*)(qp + (size_t)(j0 + row) * HD + ch * 8);
    }
    if (tid < 64) zsh[tid] = 0.f;

    float s[2][2] = {{0.f, 0.f}, {0.f, 0.f}};
    int buf = 0;

    for (int kt = 0; kt < NKT; kt++) {
        CP_WAIT0();
        __syncthreads();

        if (kt + 1 < NKT) {
            int kbase = (kt + 1) * 128;
#pragma unroll
            for (int r = 0; r < 2; r++) {
                int task = tid + 256 * r;
                int row = task >> 2, ch = task & 3;
                int col = kbase + row;
                if (col < L)
                    cp16(&ks[buf ^ 1][row][ch * 8], kp + (size_t)col * HD + ch * 8);
            }
            CP_COMMIT();
        }

        float e[2][4][4];
#pragma unroll
        for (int mt = 0; mt < 2; mt++)
#pragma unroll
            for (int nt = 0; nt < 4; nt++)
#pragma unroll
                for (int c = 0; c < 4; c++) e[mt][nt][c] = 0.f;

#pragma unroll
        for (int s16 = 0; s16 < 2; s16++) {
            int kd = s16 * 16;
            unsigned a[2][4];
#pragma unroll
            for (int mt = 0; mt < 2; mt++) {
                int r = m0 + mt * 16 + g;
                a[mt][0] = ldh2(&qs[r    ][kd + 2 * t    ]);
                a[mt][1] = ldh2(&qs[r + 8][kd + 2 * t    ]);
                a[mt][2] = ldh2(&qs[r    ][kd + 2 * t + 8]);
                a[mt][3] = ldh2(&qs[r + 8][kd + 2 * t + 8]);
            }
#pragma unroll
            for (int nt = 0; nt < 4; nt++) {
                int n = nb + nt * 8 + g;
                unsigned b0 = ldh2(&ks[buf][n][kd + 2 * t    ]);
                unsigned b1 = ldh2(&ks[buf][n][kd + 2 * t + 8]);
                mma_f16(e[0][nt], a[0][0], a[0][1], a[0][2], a[0][3], b0, b1);
                mma_f16(e[1][nt], a[1][0], a[1][1], a[1][2], a[1][3], b0, b1);
            }
        }

        if (kt < NKT - 1 || wk < 2) {
#pragma unroll
            for (int mt = 0; mt < 2; mt++)
#pragma unroll
                for (int nt = 0; nt < 4; nt++) {
                    s[mt][0] += ex2(e[mt][nt][0]) + ex2(e[mt][nt][1]);
                    s[mt][1] += ex2(e[mt][nt][2]) + ex2(e[mt][nt][3]);
                }
        }
        buf ^= 1;
    }

#pragma unroll
    for (int mask = 1; mask <= 2; mask <<= 1)
#pragma unroll
        for (int mt = 0; mt < 2; mt++)
#pragma unroll
            for (int r = 0; r < 2; r++)
                s[mt][r] += __shfl_xor_sync(0xffffffffu, s[mt][r], mask);
    if (t == 0) {
        atomicAdd(&zsh[m0 + g     ], s[0][0]);
        atomicAdd(&zsh[m0 + g + 8 ], s[0][1]);
        atomicAdd(&zsh[m0 + g + 16], s[1][0]);
        atomicAdd(&zsh[m0 + g + 24], s[1][1]);
    }
    __syncthreads();
    if (tid < 64) g_lz[bg * L + j0 + tid] = -log2f(zsh[tid]);
}

// ---------------------------------------------------------------------------
// Kernel 3: out[d,k] = sum_j exp2(e[j,k] + lz_j) * v[d,j]  (+ x residual)
// grid (25 k-tiles, 32 bg), block 256, dynamic smem (~74.5 KB).
// SINGLE barrier per iter: QK(t) and PV(t-1) and exp(t) share one interval so
// tensor and MUFU overlap across warps. psT double-buffered; ws 4-buffered
// (PV lags the cp.async prefetch by 2).
// QK computes E^T (A=K, B=Q). Warp (w>>1: 32k, w&1: 32j).
// PV: kh=w>>2 (j-half), wm=(w>>1)&1 (16 d rows), wn=w&1 (64 k cols).
// ---------------------------------------------------------------------------
__global__ void __launch_bounds__(256) pass2_kernel(const float* __restrict__ x,
                                                    float* __restrict__ out)
{
    extern __shared__ __half smh[];
    __half (*ks2)[40] = (__half(*)[40])smh;                   // 128 x 40      (5120 h)
    __half (*qs)[40]  = (__half(*)[40])(smh + 5120);          // 2 x 64 x 40   (5120 h)
    __half (*ws)[72]  = (__half(*)[72])(smh + 10240);         // 4 x 32 x 72   (9216 h)
    __half (*psT)[72] = (__half(*)[72])(smh + 19456);         // 2 x 128 x 72  (18432 h)
    float* lzsh       = (float*)(smh + 37888);                // 2 x 64 floats (512 B)
    float* red        = (float*)psT;                           // epilogue scratch [32][130]

    int bg = blockIdx.y;
    int k0 = blockIdx.x * 128;
    int tid = threadIdx.x;
    int w = tid >> 5, lane = tid & 31;
    int g = lane >> 2, t = lane & 3;
    int mE = (w >> 1) * 32;            // E^T k-base for this warp
    int nE = (w & 1) * 32;             // E^T j-base
    int kh = w >> 2, wm = (w >> 1) & 1, wn = w & 1;
    int m0p = wm * 16, nbp = wn * 64;

    const __half* qp  = g_qh + (size_t)bg * L * HD;
    const __half* kp  = g_kh + (size_t)bg * L * HD;
    const __half* vp  = g_vh + (size_t)bg * HD * L;
    const float*  lzp = g_lz + bg * L;

    {
        int row = tid >> 2, ch = tid & 3;
        cp16(&qs[row][ch * 8], qp + (size_t)row * HD + ch * 8);
        int vrow = tid >> 3, vch = tid & 7;
        cp16(&ws[vrow][vch * 8], vp + (size_t)vrow * L + vch * 8);
        if (tid < 16) cp16(&lzsh[tid * 4], lzp + tid * 4);
        CP_COMMIT();
    }

#pragma unroll
    for (int r = 0; r < 2; r++) {
        int task = tid + 256 * r;
        int row = task >> 2, ch = task & 3;
        int col = k0 + row;
        if (col < L)
            *(uint4*)&ks2[row][ch * 8] = *(const uint4*)(kp + (size_t)col * HD + ch * 8);
        else
            *(uint4*)&ks2[row][ch * 8] = make_uint4(0, 0, 0, 0);
    }

    float acc[8][4];
#pragma unroll
    for (int nt = 0; nt < 8; nt++)
#pragma unroll
        for (int c = 0; c < 4; c++) acc[nt][c] = 0.f;

    int buf = 0, pb = 0;
    for (int jt = 0; jt < NT; jt++) {
        CP_WAIT0();
        __syncthreads();   // tiles(jt) ready; psT[pb^1] (written jt-1) visible;
                           // psT[pb] free (its readers PV(jt-2) ran pre-barrier)

        if (jt + 1 < NT) {
            int jn = (jt + 1) * 64;
            int ob = buf ^ 1;
            int row = tid >> 2, ch = tid & 3;
            cp16(&qs[ob * 64 + row][ch * 8], qp + (size_t)(jn + row) * HD + ch * 8);
            int vrow = tid >> 3, vch = tid & 7;
            cp16(&ws[((jt + 1) & 3) * 32 + vrow][vch * 8], vp + (size_t)vrow * L + jn + vch * 8);
            if (tid < 16) cp16(&lzsh[ob * 64 + tid * 4], lzp + jn + tid * 4);
            CP_COMMIT();
        }

        // ---- QK(t): E^T = K Q^T tile (128k x 64j): A = K (m=k), B = Q (n=j) ----
        float e[2][4][4];
#pragma unroll
        for (int mt = 0; mt < 2; mt++)
#pragma unroll
            for (int nt = 0; nt < 4; nt++)
#pragma unroll
                for (int c = 0; c < 4; c++) e[mt][nt][c] = 0.f;

#pragma unroll
        for (int s16 = 0; s16 < 2; s16++) {
            int kd = s16 * 16;
            unsigned a[2][4];
#pragma unroll
            for (int mt = 0; mt < 2; mt++) {
                int r = mE + mt * 16 + g;
                a[mt][0] = ldh2(&ks2[r    ][kd + 2 * t    ]);
                a[mt][1] = ldh2(&ks2[r + 8][kd + 2 * t    ]);
                a[mt][2] = ldh2(&ks2[r    ][kd + 2 * t + 8]);
                a[mt][3] = ldh2(&ks2[r + 8][kd + 2 * t + 8]);
            }
#pragma unroll
            for (int nt = 0; nt < 4; nt++) {
                int n = buf * 64 + nE + nt * 8 + g;
                unsigned b0 = ldh2(&qs[n][kd + 2 * t    ]);
                unsigned b1 = ldh2(&qs[n][kd + 2 * t + 8]);
                mma_f16(e[0][nt], a[0][0], a[0][1], a[0][2], a[0][3], b0, b1);
                mma_f16(e[1][nt], a[1][0], a[1][1], a[1][2], a[1][3], b0, b1);
            }
        }

        // ---- PV(t-1): acc += V * P using psT[pb^1], ws[(jt-1)&3] ----
        if (jt > 0) {
            int wb = ((jt - 1) & 3) * 32;
            int po = (pb ^ 1) * 128;
#pragma unroll
            for (int s16 = 0; s16 < 2; s16++) {
                int kd = kh * 32 + s16 * 16;
                unsigned a0 = ldh2(&ws[wb + m0p + g    ][kd + 2 * t    ]);
                unsigned a1 = ldh2(&ws[wb + m0p + g + 8][kd + 2 * t    ]);
                unsigned a2 = ldh2(&ws[wb + m0p + g    ][kd + 2 * t + 8]);
                unsigned a3 = ldh2(&ws[wb + m0p + g + 8][kd + 2 * t + 8]);
#pragma unroll
                for (int nt = 0; nt < 8; nt++) {
                    int n = po + nbp + nt * 8 + g;
                    unsigned b0 = ldh2(&psT[n][kd + 2 * t    ]);
                    unsigned b1 = ldh2(&psT[n][kd + 2 * t + 8]);
                    mma_f16(acc[nt], a0, a1, a2, a3, b0, b1);
                }
            }
        }

        // ---- exp(t): P = exp2(E + lz_j) <= 1 -> psT[pb], packed STS.32 ----
#pragma unroll
        for (int nt = 0; nt < 4; nt++) {
            int jc = nE + nt * 8 + 2 * t;
            float lz0 = lzsh[buf * 64 + jc];
            float lz1 = lzsh[buf * 64 + jc + 1];
#pragma unroll
            for (int mt = 0; mt < 2; mt++) {
                int kr = pb * 128 + mE + mt * 16 + g;
                __half2 p0 = __floats2half2_rn(ex2(e[mt][nt][0] + lz0),
                                               ex2(e[mt][nt][1] + lz1));
                __half2 p1 = __floats2half2_rn(ex2(e[mt][nt][2] + lz0),
                                               ex2(e[mt][nt][3] + lz1));
                *(__half2*)&psT[kr    ][jc] = p0;
                *(__half2*)&psT[kr + 8][jc] = p1;
            }
        }

        buf ^= 1; pb ^= 1;
    }

    // ---- tail PV(NT-1): psT[pb^1], ws[(NT-1)&3] ----
    __syncthreads();
    {
        int wb = ((NT - 1) & 3) * 32;
        int po = (pb ^ 1) * 128;
#pragma unroll
        for (int s16 = 0; s16 < 2; s16++) {
            int kd = kh * 32 + s16 * 16;
            unsigned a0 = ldh2(&ws[wb + m0p + g    ][kd + 2 * t    ]);
            unsigned a1 = ldh2(&ws[wb + m0p + g + 8][kd + 2 * t    ]);
            unsigned a2 = ldh2(&ws[wb + m0p + g    ][kd + 2 * t + 8]);
            unsigned a3 = ldh2(&ws[wb + m0p + g + 8][kd + 2 * t + 8]);
#pragma unroll
            for (int nt = 0; nt < 8; nt++) {
                int n = po + nbp + nt * 8 + g;
                unsigned b0 = ldh2(&psT[n][kd + 2 * t    ]);
                unsigned b1 = ldh2(&psT[n][kd + 2 * t + 8]);
                mma_f16(acc[nt], a0, a1, a2, a3, b0, b1);
            }
        }
    }

    // ---- split-K reduction across kh pairs (reuse psT region as fp32 scratch) ----
    __syncthreads();
    if (kh == 1) {
#pragma unroll
        for (int nt = 0; nt < 8; nt++) {
            int col = nbp + nt * 8 + 2 * t;
            *(float2*)&red[(m0p + g    ) * 130 + col] = make_float2(acc[nt][0], acc[nt][1]);
            *(float2*)&red[(m0p + g + 8) * 130 + col] = make_float2(acc[nt][2], acc[nt][3]);
        }
    }
    __syncthreads();
    if (kh == 0) {
        int b = bg >> 3, gh = bg & 7;
#pragma unroll
        for (int nt = 0; nt < 8; nt++) {
            int col = nbp + nt * 8 + 2 * t;
            float2 r0 = *(float2*)&red[(m0p + g    ) * 130 + col];
            float2 r1 = *(float2*)&red[(m0p + g + 8) * 130 + col];
            int gcol = k0 + col;
            if (gcol < L) {
                size_t b0 = ((size_t)b * CH + gh * HD + m0p + g) * L + gcol;
                size_t b1 = b0 + (size_t)8 * L;
                out[b0    ] = acc[nt][0] + r0.x + x[b0    ];
                out[b0 + 1] = acc[nt][1] + r0.y + x[b0 + 1];
                out[b1    ] = acc[nt][2] + r1.x + x[b1    ];
                out[b1 + 1] = acc[nt][3] + r1.y + x[b1 + 1];
            }
        }
    }
}

// ---------------------------------------------------------------------------
extern "C" void kernel_launch(void* const* d_in, const int* in_sizes, int n_in,
                              void* d_out, int out_size)
{
    (void)in_sizes; (void)n_in; (void)out_size;
    const float* x  = (const float*)d_in[0];
    const float* Wq = (const float*)d_in[1];
    const float* bq = (const float*)d_in[2];
    const float* Wk = (const float*)d_in[3];
    const float* bk = (const float*)d_in[4];
    const float* Wv = (const float*)d_in[5];
    const float* bv = (const float*)d_in[6];
    float* out = (float*)d_out;

    const int SMEM2 = 37888 * 2 + 512 + 128;   // halves + lz floats + slack
    cudaFuncSetAttribute(pass2_kernel, cudaFuncAttributeMaxDynamicSharedMemorySize, SMEM2);

    qkv_kernel<<<dim3(NT, BG), 256>>>(x, Wq, bq, Wk, bk, Wv, bv);
    pass1_kernel<<<dim3(NT, BG), 256>>>();
    pass2_kernel<<<dim3(NKT, BG), 256, SMEM2>>>(x, out);
}